// round 10
// baseline (speedup 1.0000x reference)
#include <cuda_runtime.h>

#define FULL 0xFFFFFFFFu

// Problem constants
#define BATCH 32
#define IN    2048
#define OUT   2048
#define KNUM  8
#define HDIM  512
#define KSZ   (IN * OUT)          // 4M elements per expert

#define IBLK   512                // i-range per main block (4 x 128 halves)
#define NCHUNK (IN / IBLK)        // 4
#define OBLK   8                  // o's per block (8 warps x 1 o)
#define NOBLK  (OUT / OBLK)       // 256
#define XSTR   516                // x_s row stride (conflict-free LDS.128)

// Scratch (device globals; returned to initial state every call -> replay safe)
__device__ float    g_h[HDIM];        // zero-init; re-zeroed by last block
__device__ unsigned g_ticket;         // zero-init; reset by last block
__device__ float    g_alpha[KNUM];

// ---------------------------------------------------------------------------
// Fused MLP (single launch): 128 blocks x 512 thr. Partial cond@w1 -> atomic
// into g_h; zero out-slice. Last block (ticket) finishes relu/w2/softmax and
// resets scratch for graph replay.
// ---------------------------------------------------------------------------
__global__ void mlp_kernel(const float* __restrict__ cond,
                           const float* __restrict__ w1,
                           const float* __restrict__ b1,
                           const float* __restrict__ w2,
                           const float* __restrict__ b2,
                           float* __restrict__ out) {
    __shared__ float    h_s[HDIM];
    __shared__ float    s_s[KNUM];
    __shared__ unsigned rank_s;

    int j  = threadIdx.x;         // 0..511
    int p  = blockIdx.x;          // 0..127
    int i0 = p * 16;

    float s[8];
#pragma unroll
    for (int u = 0; u < 8; ++u)
        s[u] = cond[i0 + u] * w1[(i0 + u) * HDIM + j];
#pragma unroll
    for (int u = 0; u < 8; ++u)
        s[u] += cond[i0 + 8 + u] * w1[(i0 + 8 + u) * HDIM + j];
    float sum = ((s[0] + s[1]) + (s[2] + s[3])) + ((s[4] + s[5]) + (s[6] + s[7]));

    atomicAdd(&g_h[j], sum);
    out[p * HDIM + j] = 0.f;      // zero out for main's atomic accumulation

    __threadfence();
    __syncthreads();
    if (j == 0) rank_s = atomicAdd(&g_ticket, 1u);
    __syncthreads();
    if (rank_s != gridDim.x - 1) return;

    __threadfence();
    h_s[j] = fmaxf(g_h[j] + b1[j], 0.f);
    __syncthreads();

    int wid = j >> 5, lane = j & 31;
    if (wid < KNUM) {
        float sc = 0.f;
#pragma unroll
        for (int m = 0; m < HDIM / 32; ++m) {
            int jj = lane + m * 32;
            sc += h_s[jj] * w2[jj * KNUM + wid];
        }
#pragma unroll
        for (int off = 16; off; off >>= 1) sc += __shfl_xor_sync(FULL, sc, off);
        if (lane == 0) s_s[wid] = sc + b2[wid];
    }
    __syncthreads();
    if (j == 0) {
        float mx = -1e30f;
#pragma unroll
        for (int k = 0; k < KNUM; ++k) mx = fmaxf(mx, s_s[k]);
        float e[KNUM];
        float ssum = 0.f;
#pragma unroll
        for (int k = 0; k < KNUM; ++k) { e[k] = __expf(s_s[k] - mx); ssum += e[k]; }
        float inv = 1.f / ssum;
#pragma unroll
        for (int k = 0; k < KNUM; ++k) g_alpha[k] = e[k] * inv;
        g_ticket = 0;             // reset for next replay
    }
    g_h[j] = 0.f;                 // reset for next replay
}

// ---------------------------------------------------------------------------
// Main: out[b,o] (+)= sum_{i in chunk} (sum_k a_k KW[k,o,i]) * x[b,i]
// grid = NCHUNK*NOBLK = 1024 blocks x 256 threads (8 warps x 1 o each).
// 2-half-deep circular register pipeline: cur[2][8] holds halves h and h+1;
// consuming half h reloads its buffer with half h+2 -> loads land ~2 compute
// phases before use (covers loaded-DRAM latency). lane = batch row b.
// ---------------------------------------------------------------------------
__global__ __launch_bounds__(256) void main_kernel(
        const float* __restrict__ x,    // [32, 2048]
        const float* __restrict__ kw,   // [8, 2048, 2048]
        const float* __restrict__ kb,   // [8, 2048]
        float* __restrict__ out) {      // [32, 2048]
    extern __shared__ float sm[];
    float* x_s   = sm;                            // 32 * 516 = 16512 floats
    float* w_s   = sm + BATCH * XSTR;             // 8 warps * 128 = 1024
    float* out_s = w_s;                           // aliased (used after sync)
    float* a_s   = w_s + 8 * 128;                 // 8

    int t    = threadIdx.x;
    int wid  = t >> 5;
    int lane = t & 31;
    int ob   = blockIdx.x & (NOBLK - 1);          // 0..255
    int c    = blockIdx.x >> 8;                   // 0..3
    int i0   = c * IBLK;
    int o    = ob * OBLK + wid;                   // this warp's single o

    if (t < KNUM) a_s[t] = g_alpha[t];

    const float* base = kw + (size_t)o * IN + i0 + lane * 4;

    // fill the 2-deep pipeline: buffer 0 = half 0 (before x staging),
    // buffer 1 = half 1 (right after, still ahead of any consumption)
    float4 cur[2][KNUM];
#pragma unroll
    for (int k = 0; k < KNUM; ++k)
        cur[0][k] = *reinterpret_cast<const float4*>(base + (size_t)k * KSZ);
#pragma unroll
    for (int k = 0; k < KNUM; ++k)
        cur[1][k] = *reinterpret_cast<const float4*>(base + (size_t)k * KSZ + 128);

    // stage x tile: x_s[b][il] = x[b][i0+il], float4 (full 512-i tile)
    const float4* x4 = reinterpret_cast<const float4*>(x);
#pragma unroll
    for (int jj = 0; jj < (BATCH * IBLK) / (4 * 256); ++jj) {
        int idx = jj * 256 + t;                   // 0..4095 float4 units
        int b   = idx >> 7;                       // 128 f4 per row
        int il4 = idx & 127;
        *reinterpret_cast<float4*>(&x_s[b * XSTR + il4 * 4]) =
            x4[(b * IN + i0) / 4 + il4];
    }
    __syncthreads();

    float4 acc = make_float4(0.f, 0.f, 0.f, 0.f);

#pragma unroll
    for (int h = 0; h < IBLK / 128; ++h) {
        int buf = h & 1;

        // ---- aggregate experts from this half's buffer ----
        float4 w4 = make_float4(0.f, 0.f, 0.f, 0.f);
#pragma unroll
        for (int k = 0; k < KNUM; ++k) {
            float ak = a_s[k];
            w4.x += ak * cur[buf][k].x; w4.y += ak * cur[buf][k].y;
            w4.z += ak * cur[buf][k].z; w4.w += ak * cur[buf][k].w;
        }

        // ---- refill this buffer with half h+2 (lands 2 phases later) ----
        if (h < IBLK / 128 - 2) {
            int off = (h + 2) * 128;
#pragma unroll
            for (int k = 0; k < KNUM; ++k)
                cur[buf][k] = *reinterpret_cast<const float4*>(
                                  base + (size_t)k * KSZ + off);
        }

        // ---- stage aggregated strip (warp-private row) ----
        *reinterpret_cast<float4*>(&w_s[wid * 128 + lane * 4]) = w4;
        __syncwarp();

        // ---- compute: lane = b; 4 i per iter ----
#pragma unroll
        for (int src = 0; src < 32; ++src) {
            float4 xq = *reinterpret_cast<const float4*>(
                            &x_s[lane * XSTR + h * 128 + src * 4]);
            float4 wq = *reinterpret_cast<const float4*>(
                            &w_s[wid * 128 + src * 4]);
            acc.x += wq.x * xq.x; acc.y += wq.y * xq.y;
            acc.z += wq.z * xq.z; acc.w += wq.w * xq.w;
        }
        __syncwarp();   // before w_s overwrite next half
    }

    // ---- epilogue: bias (c==0 only), transpose via w_s alias, atomic add ----
    float bb = 0.f;
    if (c == 0) {
#pragma unroll
        for (int k = 0; k < KNUM; ++k) bb += a_s[k] * kb[k * OUT + o];
    }
    float v = (acc.x + acc.y) + (acc.z + acc.w) + bb;

    __syncthreads();                 // all warps done reading w_s
    out_s[lane * 9 + wid] = v;       // lane = b, 8 o per block (stride 9)
    __syncthreads();
    {
        int b  = t >> 3;             // 0..31
        int oi = t & 7;              // 0..7
        atomicAdd(&out[b * OUT + ob * OBLK + oi], out_s[b * 9 + oi]);
    }
}

// ---------------------------------------------------------------------------
extern "C" void kernel_launch(void* const* d_in, const int* in_sizes, int n_in,
                              void* d_out, int out_size) {
    const float* x    = (const float*)d_in[0];
    const float* cond = (const float*)d_in[1];
    const float* w1   = (const float*)d_in[2];
    const float* b1   = (const float*)d_in[3];
    const float* w2   = (const float*)d_in[4];
    const float* b2   = (const float*)d_in[5];
    const float* kw   = (const float*)d_in[6];
    const float* kb   = (const float*)d_in[7];
    float* out = (float*)d_out;

    const int SMEM_MAIN = (BATCH * XSTR + 8 * 128 + 8) * 4;  // ~70.2 KB
    static int smem_set = 0;
    if (!smem_set) {
        cudaFuncSetAttribute(main_kernel,
                             cudaFuncAttributeMaxDynamicSharedMemorySize,
                             SMEM_MAIN);
        smem_set = 1;
    }

    mlp_kernel<<<128, HDIM>>>(cond, w1, b1, w2, b2, out);
    main_kernel<<<NCHUNK * NOBLK, 256, SMEM_MAIN>>>(x, kw, kb, out);
}

// round 11
// speedup vs baseline: 1.2860x; 1.2860x over previous
#include <cuda_runtime.h>

#define FULL 0xFFFFFFFFu

// Problem constants
#define BATCH 32
#define IN    2048
#define OUT   2048
#define KNUM  8
#define HDIM  512
#define KSZ   (IN * OUT)          // 4M elements per expert

#define IBLK   512                // i-range per main block
#define NCHUNK (IN / IBLK)        // 4
#define NQ     (IBLK / 64)        // 8 quarters of 64 i
#define OBLK   16                 // o's per block (8 warps x 2 o)
#define NOBLK  (OUT / OBLK)       // 128
#define XSTR   516                // x_s row stride

// Scratch (device globals; returned to initial state every call -> replay safe)
__device__ float    g_h[HDIM];        // zero-init; re-zeroed by last block
__device__ unsigned g_ticket;         // zero-init; reset by last block
__device__ float    g_alpha[KNUM];

// ---------------------------------------------------------------------------
// Fused MLP (single launch): 128 blocks x 512 thr. Partial cond@w1 -> atomic
// into g_h; zero out-slice. Last block (ticket) finishes relu/w2/softmax and
// resets scratch for graph replay.
// ---------------------------------------------------------------------------
__global__ void mlp_kernel(const float* __restrict__ cond,
                           const float* __restrict__ w1,
                           const float* __restrict__ b1,
                           const float* __restrict__ w2,
                           const float* __restrict__ b2,
                           float* __restrict__ out) {
    __shared__ float    h_s[HDIM];
    __shared__ float    s_s[KNUM];
    __shared__ unsigned rank_s;

    int j  = threadIdx.x;         // 0..511
    int p  = blockIdx.x;          // 0..127
    int i0 = p * 16;

    float s[8];
#pragma unroll
    for (int u = 0; u < 8; ++u)
        s[u] = cond[i0 + u] * w1[(i0 + u) * HDIM + j];
#pragma unroll
    for (int u = 0; u < 8; ++u)
        s[u] += cond[i0 + 8 + u] * w1[(i0 + 8 + u) * HDIM + j];
    float sum = ((s[0] + s[1]) + (s[2] + s[3])) + ((s[4] + s[5]) + (s[6] + s[7]));

    atomicAdd(&g_h[j], sum);
    out[p * HDIM + j] = 0.f;      // zero out for main's atomic accumulation

    __threadfence();
    __syncthreads();
    if (j == 0) rank_s = atomicAdd(&g_ticket, 1u);
    __syncthreads();
    if (rank_s != gridDim.x - 1) return;

    __threadfence();
    h_s[j] = fmaxf(g_h[j] + b1[j], 0.f);
    __syncthreads();

    int wid = j >> 5, lane = j & 31;
    if (wid < KNUM) {
        float sc = 0.f;
#pragma unroll
        for (int m = 0; m < HDIM / 32; ++m) {
            int jj = lane + m * 32;
            sc += h_s[jj] * w2[jj * KNUM + wid];
        }
#pragma unroll
        for (int off = 16; off; off >>= 1) sc += __shfl_xor_sync(FULL, sc, off);
        if (lane == 0) s_s[wid] = sc + b2[wid];
    }
    __syncthreads();
    if (j == 0) {
        float mx = -1e30f;
#pragma unroll
        for (int k = 0; k < KNUM; ++k) mx = fmaxf(mx, s_s[k]);
        float e[KNUM];
        float ssum = 0.f;
#pragma unroll
        for (int k = 0; k < KNUM; ++k) { e[k] = __expf(s_s[k] - mx); ssum += e[k]; }
        float inv = 1.f / ssum;
#pragma unroll
        for (int k = 0; k < KNUM; ++k) g_alpha[k] = e[k] * inv;
        g_ticket = 0;             // reset for next replay
    }
    g_h[j] = 0.f;                 // reset for next replay
}

// ---------------------------------------------------------------------------
// Main: out[b,o] (+)= sum_{i in chunk} (sum_k a_k KW[k,o,i]) * x[b,i]
// grid = NCHUNK*NOBLK = 512 blocks x 256 threads (8 warps x 2 o).
// Lane = (og = lane>>4 -> which o, io = lane&15 -> which 4-i slice).
// Aggregated weights stay in REGISTERS (no w_s round-trip, no broadcast LDS):
// per 64-i quarter: 8 LDG.128 -> w4 regs; prefetch next quarter (distance-1);
// then 32 x (1 LDS.128 of x_s[b] + 4 FMA into acc[b]). L1 bytes per DRAM
// byte drops ~7.1x -> 3.0x, removing the measured L1tex crossbar bound.
// ---------------------------------------------------------------------------
__global__ __launch_bounds__(256, 2) void main_kernel(
        const float* __restrict__ x,    // [32, 2048]
        const float* __restrict__ kw,   // [8, 2048, 2048]
        const float* __restrict__ kb,   // [8, 2048]
        float* __restrict__ out) {      // [32, 2048]
    extern __shared__ float sm[];
    float* x_s    = sm;                           // 32 * 516 floats (66 KB)
    float* a_s    = sm + BATCH * XSTR;            // 8
    float* part_s = sm;                           // alias x_s after compute:
                                                  // [ (b*16+oi)*17 + io ]

    int t    = threadIdx.x;
    int wid  = t >> 5;
    int lane = t & 31;
    int io   = lane & 15;
    int og   = lane >> 4;
    int ob   = blockIdx.x & (NOBLK - 1);          // 0..127
    int c    = blockIdx.x >> 7;                   // 0..3
    int i0   = c * IBLK;
    int oi   = wid * 2 + og;                      // 0..15 within block
    int o    = ob * OBLK + oi;

    if (t < KNUM) a_s[t] = g_alpha[t];

    // thread's kw base: its o row, its 4-i slice of quarter 0
    const float* base = kw + (size_t)o * IN + i0 + io * 4;

    // preload quarter 0 (8 experts) BEFORE x staging
    float4 cur[KNUM];
#pragma unroll
    for (int k = 0; k < KNUM; ++k)
        cur[k] = *reinterpret_cast<const float4*>(base + (size_t)k * KSZ);

    // stage x tile: x_s[b][il] = x[b][i0+il], float4 (full 512-i tile)
    const float4* x4 = reinterpret_cast<const float4*>(x);
#pragma unroll
    for (int jj = 0; jj < (BATCH * IBLK) / (4 * 256); ++jj) {
        int idx = jj * 256 + t;                   // 0..4095 float4 units
        int b   = idx >> 7;                       // 128 f4 per row
        int il4 = idx & 127;
        *reinterpret_cast<float4*>(&x_s[b * XSTR + il4 * 4]) =
            x4[(b * IN + i0) / 4 + il4];
    }
    __syncthreads();

    float a[KNUM];
#pragma unroll
    for (int k = 0; k < KNUM; ++k) a[k] = a_s[k];

    float acc[BATCH];
#pragma unroll
    for (int b = 0; b < BATCH; ++b) acc[b] = 0.f;

    for (int q = 0; q < NQ; ++q) {                // rolled: small I-cache body
        // ---- aggregate experts into registers (consumes cur) ----
        float4 w4;
        w4.x = a[0] * cur[0].x; w4.y = a[0] * cur[0].y;
        w4.z = a[0] * cur[0].z; w4.w = a[0] * cur[0].w;
#pragma unroll
        for (int k = 1; k < KNUM; ++k) {
            float ak = a[k];
            w4.x += ak * cur[k].x; w4.y += ak * cur[k].y;
            w4.z += ak * cur[k].z; w4.w += ak * cur[k].w;
        }

        // ---- prefetch next quarter (lands during this quarter's compute) ----
        if (q < NQ - 1) {
            const float* nb = base + (q + 1) * 64;
#pragma unroll
            for (int k = 0; k < KNUM; ++k)
                cur[k] = *reinterpret_cast<const float4*>(nb + (size_t)k * KSZ);
        }

        // ---- compute: 32 batches x (1 LDS.128 + 4 FMA), w in regs ----
        const float* xrow = x_s + q * 64 + io * 4;
#pragma unroll
        for (int b = 0; b < BATCH; ++b) {
            float4 xq = *reinterpret_cast<const float4*>(xrow + b * XSTR);
            acc[b] += w4.x * xq.x;
            acc[b] += w4.y * xq.y;
            acc[b] += w4.z * xq.z;
            acc[b] += w4.w * xq.w;
        }
    }

    // ---- epilogue: partials into smem (alias x_s), reduce over io ----
    __syncthreads();                  // all warps done reading x_s
#pragma unroll
    for (int b = 0; b < BATCH; ++b)
        part_s[(b * 16 + oi) * 17 + io] = acc[b];
    __syncthreads();

#pragma unroll
    for (int r = 0; r < 2; ++r) {
        int e   = r * 256 + t;        // 0..511 = b*16 + oi2
        int b   = e >> 4;
        int oi2 = e & 15;
        const float* p = &part_s[e * 17];
        float s0 = 0.f, s1 = 0.f;
#pragma unroll
        for (int j = 0; j < 16; j += 2) { s0 += p[j]; s1 += p[j + 1]; }
        float v = s0 + s1;
        if (c == 0) {                 // fold aggregated bias once
            int o2 = ob * OBLK + oi2;
            float bb = 0.f;
#pragma unroll
            for (int k = 0; k < KNUM; ++k) bb += a_s[k] * kb[k * OUT + o2];
            v += bb;
        }
        atomicAdd(&out[b * OUT + ob * OBLK + oi2], v);
    }
}

// ---------------------------------------------------------------------------
extern "C" void kernel_launch(void* const* d_in, const int* in_sizes, int n_in,
                              void* d_out, int out_size) {
    const float* x    = (const float*)d_in[0];
    const float* cond = (const float*)d_in[1];
    const float* w1   = (const float*)d_in[2];
    const float* b1   = (const float*)d_in[3];
    const float* w2   = (const float*)d_in[4];
    const float* b2   = (const float*)d_in[5];
    const float* kw   = (const float*)d_in[6];
    const float* kb   = (const float*)d_in[7];
    float* out = (float*)d_out;

    const int SMEM_MAIN = (BATCH * XSTR + 8) * 4;   // ~66 KB
    static int smem_set = 0;
    if (!smem_set) {
        cudaFuncSetAttribute(main_kernel,
                             cudaFuncAttributeMaxDynamicSharedMemorySize,
                             SMEM_MAIN);
        smem_set = 1;
    }

    mlp_kernel<<<128, HDIM>>>(cond, w1, b1, w2, b2, out);
    main_kernel<<<NCHUNK * NOBLK, 256, SMEM_MAIN>>>(x, kw, kb, out);
}